// round 9
// baseline (speedup 1.0000x reference)
#include <cuda_runtime.h>
#include <cstdint>

#define N_NODES 40000
#define N_EDGES 640000
#define D 128
#define N_OPS 5
#define EPS 1e-5f
#define STAT_BLOCKS 320
#define FLT_BIG 3.402823466e38f
#define SCAN_BLOCKS 160
#define SCAN_CHUNK 250           // SCAN_BLOCKS * SCAN_CHUNK == N_NODES

// ---------------- scratch (static device globals; no runtime allocation) ---
__device__ int   g_is32;              // 1 if edge_index is int32, 0 if int64
__device__ int   g_deg[N_NODES];
__device__ int   g_offs[N_NODES + 1];
__device__ int   g_cursor[N_NODES];
__device__ int   g_csr_src[N_EDGES];
__device__ int   g_bsum[SCAN_BLOCKS];
__device__ int   g_boff[SCAN_BLOCKS];
__device__ float g_sum[(size_t)N_NODES * D];
__device__ float g_max[(size_t)N_NODES * D];
__device__ float g_part[(size_t)STAT_BLOCKS * 2 * N_OPS * D];  // [blk][sum/sq][b][d]
__device__ float g_A[N_OPS * D];
__device__ float g_C[N_OPS * D];

// ---------------- 1. init: zero deg histogram + detect dtype --------------
// Grid-wide zero of g_deg; warp 0 of block 0 additionally sniffs whether
// edge_index is int32 (JAX x64-disabled) or true int64: int32 data viewed as
// int64 packs two random indices per word -> out-of-range with P ~ 1.
__global__ void k_init(const long long* __restrict__ ei) {
    int i = blockIdx.x * blockDim.x + threadIdx.x;
    if (i < N_NODES) g_deg[i] = 0;
    if (blockIdx.x == 0 && threadIdx.x < 32) {
        int lane = threadIdx.x;
        int bad = 0;
        #pragma unroll
        for (int j = 0; j < 8; j++) {
            long long v = ei[lane * 8 + j];
            bad |= (v < 0 || v >= N_NODES) ? 1 : 0;
        }
        unsigned m = __ballot_sync(0xffffffffu, bad);
        if (lane == 0) g_is32 = (m != 0u) ? 1 : 0;
    }
}

__device__ __forceinline__ int load_idx(const void* ei, int pos, int is32) {
    if (is32) return ((const int*)ei)[pos];
    return (int)((const long long*)ei)[pos];
}

// ---------------- 2. degree histogram -------------------------------------
__global__ void k_hist(const void* __restrict__ ei) {
    int e = blockIdx.x * blockDim.x + threadIdx.x;
    if (e < N_EDGES) {
        int dst = load_idx(ei, N_EDGES + e, g_is32);
        if ((unsigned)dst < N_NODES) atomicAdd(&g_deg[dst], 1);
    }
}

// ---------------- 3a. per-chunk degree sums (coalesced, 160 blocks) -------
__global__ void k_chunksum() {
    __shared__ int red[8];
    int b = blockIdx.x, tid = threadIdx.x;  // 256 threads, chunk = 250
    int base = b * SCAN_CHUNK;
    int s = (tid < SCAN_CHUNK) ? g_deg[base + tid] : 0;
    #pragma unroll
    for (int o = 16; o; o >>= 1) s += __shfl_down_sync(0xffffffffu, s, o);
    if ((tid & 31) == 0) red[tid >> 5] = s;
    __syncthreads();
    if (tid == 0) {
        int v = 0;
        #pragma unroll
        for (int i = 0; i < 8; i++) v += red[i];
        g_bsum[b] = v;
    }
}

// ---------------- 3b. exclusive scan of 160 chunk sums --------------------
__global__ void k_bscan() {
    __shared__ int sm[SCAN_BLOCKS];
    int tid = threadIdx.x;  // 192 threads
    if (tid < SCAN_BLOCKS) sm[tid] = g_bsum[tid];
    __syncthreads();
    if (tid == 0) {
        int run = 0;
        for (int i = 0; i < SCAN_BLOCKS; i++) { int d = sm[i]; sm[i] = run; run += d; }
        g_offs[N_NODES] = run;
    }
    __syncthreads();
    if (tid < SCAN_BLOCKS) g_boff[tid] = sm[tid];
}

// ---------------- 3c. apply: in-chunk exclusive scan (1 elem / thread) ----
__global__ void k_apply() {
    __shared__ int wtot[8], wexc[8];
    int b = blockIdx.x, tid = threadIdx.x;  // 256 threads, chunk = 250
    int lane = tid & 31, wid = tid >> 5;
    int base = b * SCAN_CHUNK;

    int d = (tid < SCAN_CHUNK) ? g_deg[base + tid] : 0;
    int v = d;
    #pragma unroll
    for (int o = 1; o < 32; o <<= 1) {
        int t = __shfl_up_sync(0xffffffffu, v, o);
        if (lane >= o) v += t;
    }
    if (lane == 31) wtot[wid] = v;
    __syncthreads();
    if (tid == 0) {
        int run = 0;
        #pragma unroll
        for (int i = 0; i < 8; i++) { int t = wtot[i]; wexc[i] = run; run += t; }
    }
    __syncthreads();

    if (tid < SCAN_CHUNK) {
        int off = g_boff[b] + wexc[wid] + (v - d);  // exclusive prefix
        g_offs[base + tid]   = off;
        g_cursor[base + tid] = off;
    }
}

// ---------------- 4. fill CSR source lists --------------------------------
__global__ void k_fill(const void* __restrict__ ei) {
    int e = blockIdx.x * blockDim.x + threadIdx.x;
    if (e < N_EDGES) {
        int is32 = g_is32;
        int src = load_idx(ei, e, is32);
        int dst = load_idx(ei, N_EDGES + e, is32);
        if ((unsigned)dst < N_NODES && (unsigned)src < N_NODES) {
            int pos = atomicAdd(&g_cursor[dst], 1);
            g_csr_src[pos] = src;
        }
    }
}

// ---------------- 5. per-node warp aggregation (sum + max), no atomics ----
// 8-wide edge unroll: eight independent LDG.128 per lane front-batched
// (MLP=8) to cover L2-hit latency (~230-260 cyc). Mean degree 16 -> typically
// two 8-batches per warp.
#define ACC(S, M, V) \
    S.x += V.x; S.y += V.y; S.z += V.z; S.w += V.w; \
    M.x = fmaxf(M.x, V.x); M.y = fmaxf(M.y, V.y);   \
    M.z = fmaxf(M.z, V.z); M.w = fmaxf(M.w, V.w);

__global__ void k_agg(const float* __restrict__ h) {
    int warp = (blockIdx.x * blockDim.x + threadIdx.x) >> 5;
    int lane = threadIdx.x & 31;
    if (warp >= N_NODES) return;

    int start = g_offs[warp];
    int end   = g_offs[warp + 1];

    float4 s0 = make_float4(0.f, 0.f, 0.f, 0.f), s1 = s0, s2 = s0, s3 = s0;
    float4 m0 = make_float4(-FLT_BIG, -FLT_BIG, -FLT_BIG, -FLT_BIG);
    float4 m1 = m0, m2 = m0, m3 = m0;

    const float* hp = h + lane * 4;

    for (int b = start; b < end; b += 32) {
        int idx = b + lane;
        int sv  = (idx < end) ? g_csr_src[idx] : 0;
        int cnt = min(32, end - b);
        int k = 0;
        for (; k + 8 <= cnt; k += 8) {
            int ia = __shfl_sync(0xffffffffu, sv, k);
            int ib = __shfl_sync(0xffffffffu, sv, k + 1);
            int ic = __shfl_sync(0xffffffffu, sv, k + 2);
            int id = __shfl_sync(0xffffffffu, sv, k + 3);
            int ie = __shfl_sync(0xffffffffu, sv, k + 4);
            int ifx = __shfl_sync(0xffffffffu, sv, k + 5);
            int ig = __shfl_sync(0xffffffffu, sv, k + 6);
            int ih = __shfl_sync(0xffffffffu, sv, k + 7);
            const float4 va = *reinterpret_cast<const float4*>(hp + (size_t)ia * D);
            const float4 vb = *reinterpret_cast<const float4*>(hp + (size_t)ib * D);
            const float4 vc = *reinterpret_cast<const float4*>(hp + (size_t)ic * D);
            const float4 vd = *reinterpret_cast<const float4*>(hp + (size_t)id * D);
            const float4 ve = *reinterpret_cast<const float4*>(hp + (size_t)ie * D);
            const float4 vf = *reinterpret_cast<const float4*>(hp + (size_t)ifx * D);
            const float4 vg = *reinterpret_cast<const float4*>(hp + (size_t)ig * D);
            const float4 vh = *reinterpret_cast<const float4*>(hp + (size_t)ih * D);
            ACC(s0, m0, va) ACC(s1, m1, vb) ACC(s2, m2, vc) ACC(s3, m3, vd)
            ACC(s0, m0, ve) ACC(s1, m1, vf) ACC(s2, m2, vg) ACC(s3, m3, vh)
        }
        for (; k + 2 <= cnt; k += 2) {
            int ia = __shfl_sync(0xffffffffu, sv, k);
            int ib = __shfl_sync(0xffffffffu, sv, k + 1);
            const float4 va = *reinterpret_cast<const float4*>(hp + (size_t)ia * D);
            const float4 vb = *reinterpret_cast<const float4*>(hp + (size_t)ib * D);
            ACC(s0, m0, va) ACC(s1, m1, vb)
        }
        if (k < cnt) {
            int ia = __shfl_sync(0xffffffffu, sv, k);
            const float4 va = *reinterpret_cast<const float4*>(hp + (size_t)ia * D);
            ACC(s0, m0, va)
        }
    }

    float4 s = make_float4(s0.x + s1.x + s2.x + s3.x, s0.y + s1.y + s2.y + s3.y,
                           s0.z + s1.z + s2.z + s3.z, s0.w + s1.w + s2.w + s3.w);
    float4 m = make_float4(fmaxf(fmaxf(m0.x, m1.x), fmaxf(m2.x, m3.x)),
                           fmaxf(fmaxf(m0.y, m1.y), fmaxf(m2.y, m3.y)),
                           fmaxf(fmaxf(m0.z, m1.z), fmaxf(m2.z, m3.z)),
                           fmaxf(fmaxf(m0.w, m1.w), fmaxf(m2.w, m3.w)));
    if (end == start) m = make_float4(0.f, 0.f, 0.f, 0.f);  // empty segment -> 0

    size_t o = (size_t)warp * D + lane * 4;
    *reinterpret_cast<float4*>(g_sum + o) = s;
    *reinterpret_cast<float4*>(g_max + o) = m;
}

// ---------------- 6. per-block BN partial sums (deterministic) ------------
__global__ void k_stats(const float* __restrict__ h, const float* __restrict__ hin) {
    int d   = threadIdx.x;           // 0..127
    int blk = blockIdx.x;            // 0..STAT_BLOCKS-1
    const int chunk = (N_NODES + STAT_BLOCKS - 1) / STAT_BLOCKS;  // 125
    int n0 = blk * chunk;
    int n1 = min(N_NODES, n0 + chunk);

    float s[N_OPS] = {0, 0, 0, 0, 0};
    float q[N_OPS] = {0, 0, 0, 0, 0};
    for (int n = n0; n < n1; n++) {
        size_t o = (size_t)n * D + d;
        float x0 = h[o];
        float x1 = hin[o];
        float x2 = g_sum[o];
        float inv = 1.0f / fmaxf((float)g_deg[n], 1.0f);
        float x3 = x2 * inv;
        float x4 = g_max[o];
        s[0] += x0; q[0] += x0 * x0;
        s[1] += x1; q[1] += x1 * x1;
        s[2] += x2; q[2] += x2 * x2;
        s[3] += x3; q[3] += x3 * x3;
        s[4] += x4; q[4] += x4 * x4;
    }
    size_t base = (size_t)blk * 2 * N_OPS * D;
    #pragma unroll
    for (int b = 0; b < N_OPS; b++) {
        g_part[base + b * D + d]           = s[b];
        g_part[base + (N_OPS + b) * D + d] = q[b];
    }
}

// ---------------- 7. reduce partials -> fused BN coefficients -------------
__global__ void k_coef(const float* __restrict__ w,
                       const float* __restrict__ gamma,
                       const float* __restrict__ beta) {
    int t = blockIdx.x * blockDim.x + threadIdx.x;  // (b,d) flat
    if (t >= N_OPS * D) return;
    int b = t / D;
    float S = 0.f, Q = 0.f;
    for (int g = 0; g < STAT_BLOCKS; g++) {
        size_t base = (size_t)g * 2 * N_OPS * D;
        S += g_part[base + t];
        Q += g_part[base + N_OPS * D + t];
    }
    float mu   = S * (1.0f / N_NODES);
    float var  = fmaxf(Q * (1.0f / N_NODES) - mu * mu, 0.0f);
    float rstd = rsqrtf(var + EPS);
    float A = w[b] * gamma[t] * rstd;   // weights >= 0, fold inside ReLU
    float C = w[b] * beta[t] - A * mu;
    g_A[t] = A;
    g_C[t] = C;
}

// ---------------- 8. fused normalize + ReLU + weighted sum ----------------
__global__ void k_final(const float* __restrict__ h, const float* __restrict__ hin,
                        float* __restrict__ out) {
    __shared__ float sA[N_OPS * D];
    __shared__ float sC[N_OPS * D];
    for (int i = threadIdx.x; i < N_OPS * D; i += blockDim.x) {
        sA[i] = g_A[i];
        sC[i] = g_C[i];
    }
    __syncthreads();

    int gid = blockIdx.x * blockDim.x + threadIdx.x;  // one float4 per thread
    if (gid >= N_NODES * (D / 4)) return;
    int n  = gid >> 5;
    int f4 = (gid & 31) * 4;
    size_t o = (size_t)n * D + f4;

    float4 x0 = *reinterpret_cast<const float4*>(h + o);
    float4 x1 = *reinterpret_cast<const float4*>(hin + o);
    float4 x2 = *reinterpret_cast<const float4*>(g_sum + o);
    float4 x4 = *reinterpret_cast<const float4*>(g_max + o);
    float inv = 1.0f / fmaxf((float)g_deg[n], 1.0f);
    float4 x3 = make_float4(x2.x * inv, x2.y * inv, x2.z * inv, x2.w * inv);

    float xs[N_OPS][4] = {
        {x0.x, x0.y, x0.z, x0.w},
        {x1.x, x1.y, x1.z, x1.w},
        {x2.x, x2.y, x2.z, x2.w},
        {x3.x, x3.y, x3.z, x3.w},
        {x4.x, x4.y, x4.z, x4.w},
    };
    float acc[4] = {0.f, 0.f, 0.f, 0.f};
    #pragma unroll
    for (int b = 0; b < N_OPS; b++) {
        #pragma unroll
        for (int c = 0; c < 4; c++) {
            float A = sA[b * D + f4 + c];
            float C = sC[b * D + f4 + c];
            acc[c] += fmaxf(fmaf(A, xs[b][c], C), 0.0f);
        }
    }
    *reinterpret_cast<float4*>(out + o) = make_float4(acc[0], acc[1], acc[2], acc[3]);
}

// ---------------- launch ---------------------------------------------------
extern "C" void kernel_launch(void* const* d_in, const int* in_sizes, int n_in,
                              void* d_out, int out_size) {
    const float* weights = (const float*)d_in[0];
    const void*  ei      = d_in[1];                 // int32 or int64, detected on-device
    const float* h       = (const float*)d_in[2];
    const float* hin     = (const float*)d_in[3];
    const float* gamma   = (const float*)d_in[4];
    const float* beta    = (const float*)d_in[5];
    float*       out     = (float*)d_out;

    k_init<<<(N_NODES + 255) / 256, 256>>>((const long long*)ei);
    k_hist<<<(N_EDGES + 255) / 256, 256>>>(ei);
    k_chunksum<<<SCAN_BLOCKS, 256>>>();
    k_bscan<<<1, 192>>>();
    k_apply<<<SCAN_BLOCKS, 256>>>();
    k_fill<<<(N_EDGES + 255) / 256, 256>>>(ei);
    k_agg<<<(N_NODES * 32 + 255) / 256, 256>>>(h);
    k_stats<<<STAT_BLOCKS, D>>>(h, hin);
    k_coef<<<(N_OPS * D + 255) / 256, 256>>>(weights, gamma, beta);
    k_final<<<(N_NODES * (D / 4) + 255) / 256, 256>>>(h, hin, out);
}

// round 11
// speedup vs baseline: 1.0026x; 1.0026x over previous
#include <cuda_runtime.h>
#include <cstdint>

// NOTE: round-10 bench died in the GB300 broker (container failed twice,
// kernel never ran) — identical resubmit of the fused-stats design.

#define N_NODES 40000
#define N_EDGES 640000
#define D 128
#define N_OPS 5
#define EPS 1e-5f
#define FLT_BIG 3.402823466e38f
#define SCAN_BLOCKS 160
#define SCAN_CHUNK 250           // SCAN_BLOCKS * SCAN_CHUNK == N_NODES
#define AGG_BLOCKS 1000
#define AGG_WARPS 8              // warps per agg block
#define TOT_WARPS (AGG_BLOCKS * AGG_WARPS)          // 8000
#define NODES_PER_WARP (N_NODES / TOT_WARPS)        // 5
#define PART_STRIDE (2 * N_OPS * D)                 // 1280

// ---------------- scratch (static device globals; no runtime allocation) ---
__device__ int   g_is32;              // 1 if edge_index is int32, 0 if int64
__device__ int   g_deg[N_NODES];
__device__ int   g_offs[N_NODES + 1];
__device__ int   g_cursor[N_NODES];
__device__ int   g_csr_src[N_EDGES];
__device__ int   g_bsum[SCAN_BLOCKS];
__device__ float g_sum[(size_t)N_NODES * D];
__device__ float g_max[(size_t)N_NODES * D];
__device__ float g_part[(size_t)AGG_BLOCKS * PART_STRIDE];  // [blk][s0..4|q0..4][d]
__device__ float g_A[N_OPS * D];
__device__ float g_C[N_OPS * D];

// ---------------- 1. init: zero deg histogram + detect dtype --------------
__global__ void k_init(const long long* __restrict__ ei) {
    int i = blockIdx.x * blockDim.x + threadIdx.x;
    if (i < N_NODES) g_deg[i] = 0;
    if (blockIdx.x == 0 && threadIdx.x < 32) {
        int lane = threadIdx.x;
        int bad = 0;
        #pragma unroll
        for (int j = 0; j < 8; j++) {
            long long v = ei[lane * 8 + j];
            bad |= (v < 0 || v >= N_NODES) ? 1 : 0;
        }
        unsigned m = __ballot_sync(0xffffffffu, bad);
        if (lane == 0) g_is32 = (m != 0u) ? 1 : 0;
    }
}

__device__ __forceinline__ int load_idx(const void* ei, int pos, int is32) {
    if (is32) return ((const int*)ei)[pos];
    return (int)((const long long*)ei)[pos];
}

// ---------------- 2. degree histogram -------------------------------------
__global__ void k_hist(const void* __restrict__ ei) {
    int e = blockIdx.x * blockDim.x + threadIdx.x;
    if (e < N_EDGES) {
        int dst = load_idx(ei, N_EDGES + e, g_is32);
        if ((unsigned)dst < N_NODES) atomicAdd(&g_deg[dst], 1);
    }
}

// ---------------- 3a. per-chunk degree sums -------------------------------
__global__ void k_chunksum() {
    __shared__ int red[8];
    int b = blockIdx.x, tid = threadIdx.x;  // 256 threads, chunk = 250
    int s = (tid < SCAN_CHUNK) ? g_deg[b * SCAN_CHUNK + tid] : 0;
    #pragma unroll
    for (int o = 16; o; o >>= 1) s += __shfl_down_sync(0xffffffffu, s, o);
    if ((tid & 31) == 0) red[tid >> 5] = s;
    __syncthreads();
    if (tid == 0) {
        int v = 0;
        #pragma unroll
        for (int i = 0; i < 8; i++) v += red[i];
        g_bsum[b] = v;
    }
}

// ---------------- 3b. apply: inline chunk-prefix + in-chunk scan ----------
__global__ void k_apply() {
    __shared__ int rtot[8];
    __shared__ int wtot[8], wexc[8];
    __shared__ int s_boff;
    int b = blockIdx.x, tid = threadIdx.x;  // 256 threads
    int lane = tid & 31, wid = tid >> 5;
    int base = b * SCAN_CHUNK;

    // parallel prefix of chunk sums: sum of g_bsum[i] for i < b
    int val = (tid < SCAN_BLOCKS && tid < b) ? g_bsum[tid] : 0;
    int r = val;
    #pragma unroll
    for (int o = 16; o; o >>= 1) r += __shfl_down_sync(0xffffffffu, r, o);
    if (lane == 0) rtot[wid] = r;
    __syncthreads();
    if (tid == 0) {
        int v = 0;
        #pragma unroll
        for (int i = 0; i < 8; i++) v += rtot[i];
        s_boff = v;
        if (b == SCAN_BLOCKS - 1) g_offs[N_NODES] = v + g_bsum[b];  // total
    }
    __syncthreads();

    // in-chunk exclusive scan, 1 element / thread
    int d = (tid < SCAN_CHUNK) ? g_deg[base + tid] : 0;
    int v = d;
    #pragma unroll
    for (int o = 1; o < 32; o <<= 1) {
        int t = __shfl_up_sync(0xffffffffu, v, o);
        if (lane >= o) v += t;
    }
    if (lane == 31) wtot[wid] = v;
    __syncthreads();
    if (tid == 0) {
        int run = 0;
        #pragma unroll
        for (int i = 0; i < 8; i++) { int t = wtot[i]; wexc[i] = run; run += t; }
    }
    __syncthreads();

    if (tid < SCAN_CHUNK) {
        int off = s_boff + wexc[wid] + (v - d);
        g_offs[base + tid]   = off;
        g_cursor[base + tid] = off;
    }
}

// ---------------- 4. fill CSR source lists --------------------------------
__global__ void k_fill(const void* __restrict__ ei) {
    int e = blockIdx.x * blockDim.x + threadIdx.x;
    if (e < N_EDGES) {
        int is32 = g_is32;
        int src = load_idx(ei, e, is32);
        int dst = load_idx(ei, N_EDGES + e, is32);
        if ((unsigned)dst < N_NODES && (unsigned)src < N_NODES) {
            int pos = atomicAdd(&g_cursor[dst], 1);
            g_csr_src[pos] = src;
        }
    }
}

// ---------------- 5. fused aggregation + BN partial stats -----------------
// Persistent-style: 1000 blocks x 8 warps, each warp owns 5 nodes. Warp
// gathers sum+max in registers (4-wide MLP), writes g_sum/g_max, and folds
// the node's 5 branch values into per-lane BN stat accumulators. Block
// reduces the 8 warps' stats deterministically via smem -> g_part[block].
#define ACC(S, M, V) \
    S.x += V.x; S.y += V.y; S.z += V.z; S.w += V.w; \
    M.x = fmaxf(M.x, V.x); M.y = fmaxf(M.y, V.y);   \
    M.z = fmaxf(M.z, V.z); M.w = fmaxf(M.w, V.w);

#define STAT(b, vx, vy, vz, vw) \
    st_s[b][0] += vx; st_q[b][0] += vx * vx; \
    st_s[b][1] += vy; st_q[b][1] += vy * vy; \
    st_s[b][2] += vz; st_q[b][2] += vz * vz; \
    st_s[b][3] += vw; st_q[b][3] += vw * vw;

__global__ void __launch_bounds__(256) k_agg(const float* __restrict__ h,
                                             const float* __restrict__ hin) {
    __shared__ float red[AGG_WARPS][PART_STRIDE];  // 40 KB
    int wid  = threadIdx.x >> 5;
    int lane = threadIdx.x & 31;
    int gw   = blockIdx.x * AGG_WARPS + wid;       // 0..7999

    float st_s[N_OPS][4] = {}, st_q[N_OPS][4] = {};
    const float* hp = h + lane * 4;

    for (int i = 0; i < NODES_PER_WARP; i++) {
        int node  = gw + i * TOT_WARPS;
        int start = g_offs[node];
        int end   = g_offs[node + 1];

        float4 s0 = make_float4(0.f, 0.f, 0.f, 0.f), s1 = s0;
        float4 m0 = make_float4(-FLT_BIG, -FLT_BIG, -FLT_BIG, -FLT_BIG), m1 = m0;

        for (int b = start; b < end; b += 32) {
            int idx = b + lane;
            int sv  = (idx < end) ? g_csr_src[idx] : 0;
            int cnt = min(32, end - b);
            int k = 0;
            for (; k + 4 <= cnt; k += 4) {
                int ia = __shfl_sync(0xffffffffu, sv, k);
                int ib = __shfl_sync(0xffffffffu, sv, k + 1);
                int ic = __shfl_sync(0xffffffffu, sv, k + 2);
                int id = __shfl_sync(0xffffffffu, sv, k + 3);
                const float4 va = *reinterpret_cast<const float4*>(hp + (size_t)ia * D);
                const float4 vb = *reinterpret_cast<const float4*>(hp + (size_t)ib * D);
                const float4 vc = *reinterpret_cast<const float4*>(hp + (size_t)ic * D);
                const float4 vd = *reinterpret_cast<const float4*>(hp + (size_t)id * D);
                ACC(s0, m0, va) ACC(s1, m1, vb) ACC(s0, m0, vc) ACC(s1, m1, vd)
            }
            for (; k < cnt; k++) {
                int ia = __shfl_sync(0xffffffffu, sv, k);
                const float4 va = *reinterpret_cast<const float4*>(hp + (size_t)ia * D);
                ACC(s0, m0, va)
            }
        }

        float4 s = make_float4(s0.x + s1.x, s0.y + s1.y, s0.z + s1.z, s0.w + s1.w);
        float4 m = make_float4(fmaxf(m0.x, m1.x), fmaxf(m0.y, m1.y),
                               fmaxf(m0.z, m1.z), fmaxf(m0.w, m1.w));
        if (end == start) m = make_float4(0.f, 0.f, 0.f, 0.f);

        size_t o = (size_t)node * D + lane * 4;
        *reinterpret_cast<float4*>(g_sum + o) = s;
        *reinterpret_cast<float4*>(g_max + o) = m;

        // BN stats for this node's 5 branch values (lane owns feats lane*4..+3)
        float4 x0 = *reinterpret_cast<const float4*>(h   + o);
        float4 x1 = *reinterpret_cast<const float4*>(hin + o);
        float inv = 1.0f / fmaxf((float)(end - start), 1.0f);
        STAT(0, x0.x, x0.y, x0.z, x0.w)
        STAT(1, x1.x, x1.y, x1.z, x1.w)
        STAT(2, s.x, s.y, s.z, s.w)
        STAT(3, s.x * inv, s.y * inv, s.z * inv, s.w * inv)
        STAT(4, m.x, m.y, m.z, m.w)
    }

    // deposit per-warp stats into smem, then block-reduce deterministically
    #pragma unroll
    for (int b = 0; b < N_OPS; b++) {
        #pragma unroll
        for (int c = 0; c < 4; c++) {
            red[wid][b * D + lane * 4 + c]           = st_s[b][c];
            red[wid][(N_OPS + b) * D + lane * 4 + c] = st_q[b][c];
        }
    }
    __syncthreads();
    for (int o = threadIdx.x; o < PART_STRIDE; o += 256) {
        float v = 0.f;
        #pragma unroll
        for (int w = 0; w < AGG_WARPS; w++) v += red[w][o];
        g_part[(size_t)blockIdx.x * PART_STRIDE + o] = v;
    }
}

// ---------------- 6. reduce partials -> fused BN coefficients -------------
__global__ void k_coef(const float* __restrict__ w,
                       const float* __restrict__ gamma,
                       const float* __restrict__ beta) {
    int t = blockIdx.x * blockDim.x + threadIdx.x;  // (b,d) flat, 0..639
    if (t >= N_OPS * D) return;
    int b = t / D;
    float S = 0.f, Q = 0.f;
    for (int g = 0; g + 4 <= AGG_BLOCKS; g += 4) {
        size_t b0 = (size_t)(g + 0) * PART_STRIDE;
        size_t b1 = (size_t)(g + 1) * PART_STRIDE;
        size_t b2 = (size_t)(g + 2) * PART_STRIDE;
        size_t b3 = (size_t)(g + 3) * PART_STRIDE;
        S += g_part[b0 + t] + g_part[b1 + t] + g_part[b2 + t] + g_part[b3 + t];
        Q += g_part[b0 + N_OPS * D + t] + g_part[b1 + N_OPS * D + t] +
             g_part[b2 + N_OPS * D + t] + g_part[b3 + N_OPS * D + t];
    }
    float mu   = S * (1.0f / N_NODES);
    float var  = fmaxf(Q * (1.0f / N_NODES) - mu * mu, 0.0f);
    float rstd = rsqrtf(var + EPS);
    float A = w[b] * gamma[t] * rstd;   // weights >= 0, fold inside ReLU
    float C = w[b] * beta[t] - A * mu;
    g_A[t] = A;
    g_C[t] = C;
}

// ---------------- 7. fused normalize + ReLU + weighted sum ----------------
__global__ void k_final(const float* __restrict__ h, const float* __restrict__ hin,
                        float* __restrict__ out) {
    __shared__ float sA[N_OPS * D];
    __shared__ float sC[N_OPS * D];
    for (int i = threadIdx.x; i < N_OPS * D; i += blockDim.x) {
        sA[i] = g_A[i];
        sC[i] = g_C[i];
    }
    __syncthreads();

    int gid = blockIdx.x * blockDim.x + threadIdx.x;  // one float4 per thread
    if (gid >= N_NODES * (D / 4)) return;
    int n  = gid >> 5;
    int f4 = (gid & 31) * 4;
    size_t o = (size_t)n * D + f4;

    float4 x0 = *reinterpret_cast<const float4*>(h + o);
    float4 x1 = *reinterpret_cast<const float4*>(hin + o);
    float4 x2 = *reinterpret_cast<const float4*>(g_sum + o);
    float4 x4 = *reinterpret_cast<const float4*>(g_max + o);
    float inv = 1.0f / fmaxf((float)g_deg[n], 1.0f);
    float4 x3 = make_float4(x2.x * inv, x2.y * inv, x2.z * inv, x2.w * inv);

    float xs[N_OPS][4] = {
        {x0.x, x0.y, x0.z, x0.w},
        {x1.x, x1.y, x1.z, x1.w},
        {x2.x, x2.y, x2.z, x2.w},
        {x3.x, x3.y, x3.z, x3.w},
        {x4.x, x4.y, x4.z, x4.w},
    };
    float acc[4] = {0.f, 0.f, 0.f, 0.f};
    #pragma unroll
    for (int b = 0; b < N_OPS; b++) {
        #pragma unroll
        for (int c = 0; c < 4; c++) {
            float A = sA[b * D + f4 + c];
            float C = sC[b * D + f4 + c];
            acc[c] += fmaxf(fmaf(A, xs[b][c], C), 0.0f);
        }
    }
    *reinterpret_cast<float4*>(out + o) = make_float4(acc[0], acc[1], acc[2], acc[3]);
}

// ---------------- launch ---------------------------------------------------
extern "C" void kernel_launch(void* const* d_in, const int* in_sizes, int n_in,
                              void* d_out, int out_size) {
    const float* weights = (const float*)d_in[0];
    const void*  ei      = d_in[1];                 // int32 or int64, detected on-device
    const float* h       = (const float*)d_in[2];
    const float* hin     = (const float*)d_in[3];
    const float* gamma   = (const float*)d_in[4];
    const float* beta    = (const float*)d_in[5];
    float*       out     = (float*)d_out;

    k_init<<<(N_NODES + 255) / 256, 256>>>((const long long*)ei);
    k_hist<<<(N_EDGES + 255) / 256, 256>>>(ei);
    k_chunksum<<<SCAN_BLOCKS, 256>>>();
    k_apply<<<SCAN_BLOCKS, 256>>>();
    k_fill<<<(N_EDGES + 255) / 256, 256>>>(ei);
    k_agg<<<AGG_BLOCKS, 256>>>(h, hin);
    k_coef<<<(N_OPS * D + 255) / 256, 256>>>(weights, gamma, beta);
    k_final<<<(N_NODES * (D / 4) + 255) / 256, 256>>>(h, hin, out);
}

// round 12
// speedup vs baseline: 1.1789x; 1.1758x over previous
#include <cuda_runtime.h>
#include <cstdint>

#define N_NODES 40000
#define N_EDGES 640000
#define D 128
#define N_OPS 5
#define EPS 1e-5f
#define FLT_BIG 3.402823466e38f
#define SCAN_BLOCKS 160
#define SCAN_CHUNK 250           // SCAN_BLOCKS * SCAN_CHUNK == N_NODES
#define STAT_BLOCKS 320
#define SQ_SIZE (2 * N_OPS * D)  // 1280

// ---------------- scratch (static device globals; no runtime allocation) ---
__device__ int      g_is32;           // 1 if edge_index is int32, 0 if int64
__device__ int      g_deg[N_NODES];
__device__ int      g_offs[N_NODES + 1];
__device__ int      g_cursor[N_NODES];
__device__ int      g_csr_src[N_EDGES];
__device__ unsigned g_flag[SCAN_BLOCKS];   // lookback: chunk_sum+1 (0 = not ready)
__device__ float    g_sum[(size_t)N_NODES * D];
__device__ float    g_max[(size_t)N_NODES * D];
__device__ float    g_SQ[SQ_SIZE];         // [s0..4 | q0..4][d], atomic-accumulated

// ---------------- 1. init: zero scratch + detect dtype --------------------
__global__ void k_init(const long long* __restrict__ ei) {
    int i = blockIdx.x * blockDim.x + threadIdx.x;
    if (i < N_NODES) g_deg[i] = 0;
    if (i < SQ_SIZE) g_SQ[i] = 0.0f;
    if (i < SCAN_BLOCKS) g_flag[i] = 0u;
    if (blockIdx.x == 0 && threadIdx.x < 32) {
        int lane = threadIdx.x;
        int bad = 0;
        #pragma unroll
        for (int j = 0; j < 8; j++) {
            long long v = ei[lane * 8 + j];
            bad |= (v < 0 || v >= N_NODES) ? 1 : 0;
        }
        unsigned m = __ballot_sync(0xffffffffu, bad);
        if (lane == 0) g_is32 = (m != 0u) ? 1 : 0;
    }
}

__device__ __forceinline__ int load_idx(const void* ei, int pos, int is32) {
    if (is32) return ((const int*)ei)[pos];
    return (int)((const long long*)ei)[pos];
}

// ---------------- 2. degree histogram -------------------------------------
__global__ void k_hist(const void* __restrict__ ei) {
    int e = blockIdx.x * blockDim.x + threadIdx.x;
    if (e < N_EDGES) {
        int dst = load_idx(ei, N_EDGES + e, g_is32);
        if ((unsigned)dst < N_NODES) atomicAdd(&g_deg[dst], 1);
    }
}

// ---------------- 3. single-pass exclusive scan (decoupled lookback) ------
// Each block scans its 250-node chunk, publishes chunk_sum+1 through a flag
// word (single atomic location -> value carries its own ready bit, no fence
// pairing needed), then polls all lower chunks' flags and reduces.
__global__ void k_scan() {
    __shared__ int wtot[8], wexc[8], rtot[8];
    __shared__ int s_csum, s_boff;
    int b = blockIdx.x, tid = threadIdx.x;  // 256 threads
    int lane = tid & 31, wid = tid >> 5;
    int base = b * SCAN_CHUNK;

    // in-chunk exclusive scan, 1 element / thread
    int d = (tid < SCAN_CHUNK) ? g_deg[base + tid] : 0;
    int v = d;
    #pragma unroll
    for (int o = 1; o < 32; o <<= 1) {
        int t = __shfl_up_sync(0xffffffffu, v, o);
        if (lane >= o) v += t;
    }
    if (lane == 31) wtot[wid] = v;
    __syncthreads();
    if (tid == 0) {
        int run = 0;
        #pragma unroll
        for (int i = 0; i < 8; i++) { int t = wtot[i]; wexc[i] = run; run += t; }
        s_csum = run;
        // publish this chunk's total (value+1 so 0 means "not ready")
        atomicExch(&g_flag[b], (unsigned)(run + 1));
    }
    __syncthreads();

    // lookback: thread i polls chunk i's flag (i < b), then block-reduce
    int pv = 0;
    if (tid < b) {
        unsigned f;
        do { f = atomicAdd(&g_flag[tid], 0u); } while (f == 0u);
        pv = (int)f - 1;
    }
    int r = pv;
    #pragma unroll
    for (int o = 16; o; o >>= 1) r += __shfl_down_sync(0xffffffffu, r, o);
    if (lane == 0) rtot[wid] = r;
    __syncthreads();
    if (tid == 0) {
        int s = 0;
        #pragma unroll
        for (int i = 0; i < 8; i++) s += rtot[i];
        s_boff = s;
        if (b == SCAN_BLOCKS - 1) g_offs[N_NODES] = s + s_csum;
    }
    __syncthreads();

    if (tid < SCAN_CHUNK) {
        int off = s_boff + wexc[wid] + (v - d);
        g_offs[base + tid]   = off;
        g_cursor[base + tid] = off;
    }
}

// ---------------- 4. fill CSR source lists --------------------------------
__global__ void k_fill(const void* __restrict__ ei) {
    int e = blockIdx.x * blockDim.x + threadIdx.x;
    if (e < N_EDGES) {
        int is32 = g_is32;
        int src = load_idx(ei, e, is32);
        int dst = load_idx(ei, N_EDGES + e, is32);
        if ((unsigned)dst < N_NODES && (unsigned)src < N_NODES) {
            int pos = atomicAdd(&g_cursor[dst], 1);
            g_csr_src[pos] = src;
        }
    }
}

// ---------------- 5. lean per-node warp aggregation (sum + max) -----------
// Warp per node, 4-wide edge unroll (MLP=4), no smem, low regs -> high occ.
#define ACC(S, M, V) \
    S.x += V.x; S.y += V.y; S.z += V.z; S.w += V.w; \
    M.x = fmaxf(M.x, V.x); M.y = fmaxf(M.y, V.y);   \
    M.z = fmaxf(M.z, V.z); M.w = fmaxf(M.w, V.w);

__global__ void k_agg(const float* __restrict__ h) {
    int warp = (blockIdx.x * blockDim.x + threadIdx.x) >> 5;
    int lane = threadIdx.x & 31;
    if (warp >= N_NODES) return;

    int start = g_offs[warp];
    int end   = g_offs[warp + 1];

    float4 s0 = make_float4(0.f, 0.f, 0.f, 0.f), s1 = s0;
    float4 m0 = make_float4(-FLT_BIG, -FLT_BIG, -FLT_BIG, -FLT_BIG), m1 = m0;

    const float* hp = h + lane * 4;

    for (int b = start; b < end; b += 32) {
        int idx = b + lane;
        int sv  = (idx < end) ? g_csr_src[idx] : 0;
        int cnt = min(32, end - b);
        int k = 0;
        for (; k + 4 <= cnt; k += 4) {
            int ia = __shfl_sync(0xffffffffu, sv, k);
            int ib = __shfl_sync(0xffffffffu, sv, k + 1);
            int ic = __shfl_sync(0xffffffffu, sv, k + 2);
            int id = __shfl_sync(0xffffffffu, sv, k + 3);
            const float4 va = *reinterpret_cast<const float4*>(hp + (size_t)ia * D);
            const float4 vb = *reinterpret_cast<const float4*>(hp + (size_t)ib * D);
            const float4 vc = *reinterpret_cast<const float4*>(hp + (size_t)ic * D);
            const float4 vd = *reinterpret_cast<const float4*>(hp + (size_t)id * D);
            ACC(s0, m0, va) ACC(s1, m1, vb) ACC(s0, m0, vc) ACC(s1, m1, vd)
        }
        for (; k < cnt; k++) {
            int ia = __shfl_sync(0xffffffffu, sv, k);
            const float4 va = *reinterpret_cast<const float4*>(hp + (size_t)ia * D);
            ACC(s0, m0, va)
        }
    }

    float4 s = make_float4(s0.x + s1.x, s0.y + s1.y, s0.z + s1.z, s0.w + s1.w);
    float4 m = make_float4(fmaxf(m0.x, m1.x), fmaxf(m0.y, m1.y),
                           fmaxf(m0.z, m1.z), fmaxf(m0.w, m1.w));
    if (end == start) m = make_float4(0.f, 0.f, 0.f, 0.f);  // empty segment -> 0

    size_t o = (size_t)warp * D + lane * 4;
    *reinterpret_cast<float4*>(g_sum + o) = s;
    *reinterpret_cast<float4*>(g_max + o) = m;
}

// ---------------- 6. BN stats: per-block partials -> atomic g_SQ ----------
// Thread owns feature d; accumulates 125 nodes; 10 atomicAdds per thread.
// Atomic float order-noise ~1e-7 << 1e-3 tolerance.
__global__ void k_stats(const float* __restrict__ h, const float* __restrict__ hin) {
    int d   = threadIdx.x;           // 0..127
    int blk = blockIdx.x;            // 0..STAT_BLOCKS-1
    const int chunk = N_NODES / STAT_BLOCKS;  // 125
    int n0 = blk * chunk;
    int n1 = n0 + chunk;

    float s[N_OPS] = {0, 0, 0, 0, 0};
    float q[N_OPS] = {0, 0, 0, 0, 0};
    for (int n = n0; n < n1; n++) {
        size_t o = (size_t)n * D + d;
        float x0 = h[o];
        float x1 = hin[o];
        float x2 = g_sum[o];
        float inv = 1.0f / fmaxf((float)g_deg[n], 1.0f);
        float x3 = x2 * inv;
        float x4 = g_max[o];
        s[0] += x0; q[0] += x0 * x0;
        s[1] += x1; q[1] += x1 * x1;
        s[2] += x2; q[2] += x2 * x2;
        s[3] += x3; q[3] += x3 * x3;
        s[4] += x4; q[4] += x4 * x4;
    }
    #pragma unroll
    for (int b = 0; b < N_OPS; b++) {
        atomicAdd(&g_SQ[b * D + d], s[b]);
        atomicAdd(&g_SQ[(N_OPS + b) * D + d], q[b]);
    }
}

// ---------------- 7. fused coef + normalize + ReLU + weighted sum ---------
// Each block first derives A/C from g_SQ (10 KB broadcast read), then does
// its slice of the epilogue: out = sum_b relu(A_b*x_b + C_b).
__global__ void k_final(const float* __restrict__ h, const float* __restrict__ hin,
                        const float* __restrict__ w,
                        const float* __restrict__ gamma,
                        const float* __restrict__ beta,
                        float* __restrict__ out) {
    __shared__ float sA[N_OPS * D];
    __shared__ float sC[N_OPS * D];
    for (int t = threadIdx.x; t < N_OPS * D; t += blockDim.x) {
        int b = t / D;
        float S = g_SQ[t];
        float Q = g_SQ[N_OPS * D + t];
        float mu   = S * (1.0f / N_NODES);
        float var  = fmaxf(Q * (1.0f / N_NODES) - mu * mu, 0.0f);
        float rstd = rsqrtf(var + EPS);
        float A = w[b] * gamma[t] * rstd;   // weights >= 0, fold inside ReLU
        sA[t] = A;
        sC[t] = w[b] * beta[t] - A * mu;
    }
    __syncthreads();

    int gid = blockIdx.x * blockDim.x + threadIdx.x;  // one float4 per thread
    if (gid >= N_NODES * (D / 4)) return;
    int n  = gid >> 5;
    int f4 = (gid & 31) * 4;
    size_t o = (size_t)n * D + f4;

    float4 x0 = *reinterpret_cast<const float4*>(h + o);
    float4 x1 = *reinterpret_cast<const float4*>(hin + o);
    float4 x2 = *reinterpret_cast<const float4*>(g_sum + o);
    float4 x4 = *reinterpret_cast<const float4*>(g_max + o);
    float inv = 1.0f / fmaxf((float)g_deg[n], 1.0f);
    float4 x3 = make_float4(x2.x * inv, x2.y * inv, x2.z * inv, x2.w * inv);

    float xs[N_OPS][4] = {
        {x0.x, x0.y, x0.z, x0.w},
        {x1.x, x1.y, x1.z, x1.w},
        {x2.x, x2.y, x2.z, x2.w},
        {x3.x, x3.y, x3.z, x3.w},
        {x4.x, x4.y, x4.z, x4.w},
    };
    float acc[4] = {0.f, 0.f, 0.f, 0.f};
    #pragma unroll
    for (int b = 0; b < N_OPS; b++) {
        #pragma unroll
        for (int c = 0; c < 4; c++) {
            float A = sA[b * D + f4 + c];
            float C = sC[b * D + f4 + c];
            acc[c] += fmaxf(fmaf(A, xs[b][c], C), 0.0f);
        }
    }
    *reinterpret_cast<float4*>(out + o) = make_float4(acc[0], acc[1], acc[2], acc[3]);
}

// ---------------- launch ---------------------------------------------------
extern "C" void kernel_launch(void* const* d_in, const int* in_sizes, int n_in,
                              void* d_out, int out_size) {
    const float* weights = (const float*)d_in[0];
    const void*  ei      = d_in[1];                 // int32 or int64, detected on-device
    const float* h       = (const float*)d_in[2];
    const float* hin     = (const float*)d_in[3];
    const float* gamma   = (const float*)d_in[4];
    const float* beta    = (const float*)d_in[5];
    float*       out     = (float*)d_out;

    k_init<<<(N_NODES + 255) / 256, 256>>>((const long long*)ei);
    k_hist<<<(N_EDGES + 255) / 256, 256>>>(ei);
    k_scan<<<SCAN_BLOCKS, 256>>>();
    k_fill<<<(N_EDGES + 255) / 256, 256>>>(ei);
    k_agg<<<(N_NODES * 32 + 255) / 256, 256>>>(h);
    k_stats<<<STAT_BLOCKS, D>>>(h, hin);
    k_final<<<(N_NODES * (D / 4) + 255) / 256, 256>>>(h, hin, weights, gamma, beta, out);
}

// round 13
// speedup vs baseline: 1.5189x; 1.2885x over previous
#include <cuda_runtime.h>
#include <cstdint>

#define N_NODES 40000
#define N_EDGES 640000
#define D 128
#define N_OPS 5
#define EPS 1e-5f
#define FLT_BIG 3.402823466e38f
#define SCAN_BLOCKS 160
#define SCAN_CHUNK 250           // SCAN_BLOCKS * SCAN_CHUNK == N_NODES
#define STAT_BLOCKS 320
#define STAT_CHUNK (N_NODES / STAT_BLOCKS)   // 125
#define HIST_BLOCKS 2500
#define SQ_SIZE (2 * N_OPS * D)  // 1280

// ---------------- scratch (static device globals; no runtime allocation) ---
__device__ int      g_is32;           // 1 if edge_index is int32, 0 if int64
__device__ int      g_deg[N_NODES];
__device__ int      g_offs[N_NODES + 1];
__device__ int      g_cursor[N_NODES];
__device__ int      g_csr_src[N_EDGES];
__device__ unsigned g_flag[SCAN_BLOCKS];   // lookback: chunk_sum+1 (0 = not ready)
__device__ float    g_sum[(size_t)N_NODES * D];
__device__ float    g_max[(size_t)N_NODES * D];
__device__ float    g_SQ[SQ_SIZE];         // [s0..4 | q0..4][d], atomic-accumulated

// ---------------- 1. init: zero scratch + detect dtype --------------------
__global__ void k_init(const long long* __restrict__ ei) {
    int i = blockIdx.x * blockDim.x + threadIdx.x;
    if (i < N_NODES) g_deg[i] = 0;
    if (i < SQ_SIZE) g_SQ[i] = 0.0f;
    if (i < SCAN_BLOCKS) g_flag[i] = 0u;
    if (blockIdx.x == 0 && threadIdx.x < 32) {
        int lane = threadIdx.x;
        int bad = 0;
        #pragma unroll
        for (int j = 0; j < 8; j++) {
            long long v = ei[lane * 8 + j];
            bad |= (v < 0 || v >= N_NODES) ? 1 : 0;
        }
        unsigned m = __ballot_sync(0xffffffffu, bad);
        if (lane == 0) g_is32 = (m != 0u) ? 1 : 0;
    }
}

__device__ __forceinline__ int load_idx(const void* ei, int pos, int is32) {
    if (is32) return ((const int*)ei)[pos];
    return (int)((const long long*)ei)[pos];
}

// ---------------- 2. heterogeneous: h/hin stats || degree histogram -------
// Blocks [0, STAT_BLOCKS): BN stats for graph-independent branches 0 (h) and
// 1 (hin) — they overlap with the histogram's atomic phase since blocks are
// scheduled in order and stats blocks come first.
// Blocks [STAT_BLOCKS, STAT_BLOCKS+HIST_BLOCKS): degree histogram.
__global__ void k_hist_st(const void* __restrict__ ei,
                          const float* __restrict__ h,
                          const float* __restrict__ hin) {
    if (blockIdx.x < STAT_BLOCKS) {
        int blk  = blockIdx.x;
        int d    = threadIdx.x & 127;        // feature
        int half = threadIdx.x >> 7;         // 0/1: split the node range
        int n0 = blk * STAT_CHUNK;
        float s0 = 0.f, q0 = 0.f, s1 = 0.f, q1 = 0.f;
        for (int n = n0 + half; n < n0 + STAT_CHUNK; n += 2) {
            size_t o = (size_t)n * D + d;
            float x0 = h[o];
            float x1 = hin[o];
            s0 += x0; q0 += x0 * x0;
            s1 += x1; q1 += x1 * x1;
        }
        atomicAdd(&g_SQ[0 * D + d], s0);
        atomicAdd(&g_SQ[(N_OPS + 0) * D + d], q0);
        atomicAdd(&g_SQ[1 * D + d], s1);
        atomicAdd(&g_SQ[(N_OPS + 1) * D + d], q1);
    } else {
        int e = (blockIdx.x - STAT_BLOCKS) * blockDim.x + threadIdx.x;
        if (e < N_EDGES) {
            int dst = load_idx(ei, N_EDGES + e, g_is32);
            if ((unsigned)dst < N_NODES) atomicAdd(&g_deg[dst], 1);
        }
    }
}

// ---------------- 3. single-pass exclusive scan (decoupled lookback) ------
__global__ void k_scan() {
    __shared__ int wtot[8], wexc[8], rtot[8];
    __shared__ int s_csum, s_boff;
    int b = blockIdx.x, tid = threadIdx.x;  // 256 threads
    int lane = tid & 31, wid = tid >> 5;
    int base = b * SCAN_CHUNK;

    // in-chunk exclusive scan, 1 element / thread
    int d = (tid < SCAN_CHUNK) ? g_deg[base + tid] : 0;
    int v = d;
    #pragma unroll
    for (int o = 1; o < 32; o <<= 1) {
        int t = __shfl_up_sync(0xffffffffu, v, o);
        if (lane >= o) v += t;
    }
    if (lane == 31) wtot[wid] = v;
    __syncthreads();
    if (tid == 0) {
        int run = 0;
        #pragma unroll
        for (int i = 0; i < 8; i++) { int t = wtot[i]; wexc[i] = run; run += t; }
        s_csum = run;
        atomicExch(&g_flag[b], (unsigned)(run + 1));  // publish (0 = not ready)
    }
    __syncthreads();

    // lookback: thread i polls chunk i's flag (i < b), then block-reduce
    int pv = 0;
    if (tid < b) {
        unsigned f;
        do { f = atomicAdd(&g_flag[tid], 0u); } while (f == 0u);
        pv = (int)f - 1;
    }
    int r = pv;
    #pragma unroll
    for (int o = 16; o; o >>= 1) r += __shfl_down_sync(0xffffffffu, r, o);
    if (lane == 0) rtot[wid] = r;
    __syncthreads();
    if (tid == 0) {
        int s = 0;
        #pragma unroll
        for (int i = 0; i < 8; i++) s += rtot[i];
        s_boff = s;
        if (b == SCAN_BLOCKS - 1) g_offs[N_NODES] = s + s_csum;
    }
    __syncthreads();

    if (tid < SCAN_CHUNK) {
        int off = s_boff + wexc[wid] + (v - d);
        g_offs[base + tid]   = off;
        g_cursor[base + tid] = off;
    }
}

// ---------------- 4. fill CSR source lists --------------------------------
__global__ void k_fill(const void* __restrict__ ei) {
    int e = blockIdx.x * blockDim.x + threadIdx.x;
    if (e < N_EDGES) {
        int is32 = g_is32;
        int src = load_idx(ei, e, is32);
        int dst = load_idx(ei, N_EDGES + e, is32);
        if ((unsigned)dst < N_NODES && (unsigned)src < N_NODES) {
            int pos = atomicAdd(&g_cursor[dst], 1);
            g_csr_src[pos] = src;
        }
    }
}

// ---------------- 5. lean per-node warp aggregation (sum + max) -----------
// Warp per node, 4-wide edge unroll (MLP=4), no smem, low regs -> high occ.
#define ACC(S, M, V) \
    S.x += V.x; S.y += V.y; S.z += V.z; S.w += V.w; \
    M.x = fmaxf(M.x, V.x); M.y = fmaxf(M.y, V.y);   \
    M.z = fmaxf(M.z, V.z); M.w = fmaxf(M.w, V.w);

__global__ void k_agg(const float* __restrict__ h) {
    int warp = (blockIdx.x * blockDim.x + threadIdx.x) >> 5;
    int lane = threadIdx.x & 31;
    if (warp >= N_NODES) return;

    int start = g_offs[warp];
    int end   = g_offs[warp + 1];

    float4 s0 = make_float4(0.f, 0.f, 0.f, 0.f), s1 = s0;
    float4 m0 = make_float4(-FLT_BIG, -FLT_BIG, -FLT_BIG, -FLT_BIG), m1 = m0;

    const float* hp = h + lane * 4;

    for (int b = start; b < end; b += 32) {
        int idx = b + lane;
        int sv  = (idx < end) ? g_csr_src[idx] : 0;
        int cnt = min(32, end - b);
        int k = 0;
        for (; k + 4 <= cnt; k += 4) {
            int ia = __shfl_sync(0xffffffffu, sv, k);
            int ib = __shfl_sync(0xffffffffu, sv, k + 1);
            int ic = __shfl_sync(0xffffffffu, sv, k + 2);
            int id = __shfl_sync(0xffffffffu, sv, k + 3);
            const float4 va = *reinterpret_cast<const float4*>(hp + (size_t)ia * D);
            const float4 vb = *reinterpret_cast<const float4*>(hp + (size_t)ib * D);
            const float4 vc = *reinterpret_cast<const float4*>(hp + (size_t)ic * D);
            const float4 vd = *reinterpret_cast<const float4*>(hp + (size_t)id * D);
            ACC(s0, m0, va) ACC(s1, m1, vb) ACC(s0, m0, vc) ACC(s1, m1, vd)
        }
        for (; k < cnt; k++) {
            int ia = __shfl_sync(0xffffffffu, sv, k);
            const float4 va = *reinterpret_cast<const float4*>(hp + (size_t)ia * D);
            ACC(s0, m0, va)
        }
    }

    float4 s = make_float4(s0.x + s1.x, s0.y + s1.y, s0.z + s1.z, s0.w + s1.w);
    float4 m = make_float4(fmaxf(m0.x, m1.x), fmaxf(m0.y, m1.y),
                           fmaxf(m0.z, m1.z), fmaxf(m0.w, m1.w));
    if (end == start) m = make_float4(0.f, 0.f, 0.f, 0.f);  // empty segment -> 0

    size_t o = (size_t)warp * D + lane * 4;
    *reinterpret_cast<float4*>(g_sum + o) = s;
    *reinterpret_cast<float4*>(g_max + o) = m;
}

// ---------------- 6. BN stats for graph branches 2/3/4 --------------------
// Reads only g_sum/g_max/deg (41 MB, L2-hot right after k_agg).
__global__ void k_stats2() {
    int blk  = blockIdx.x;
    int d    = threadIdx.x & 127;
    int half = threadIdx.x >> 7;
    int n0 = blk * STAT_CHUNK;

    float s2 = 0.f, q2 = 0.f, s3 = 0.f, q3 = 0.f, s4 = 0.f, q4 = 0.f;
    for (int n = n0 + half; n < n0 + STAT_CHUNK; n += 2) {
        size_t o = (size_t)n * D + d;
        float x2 = g_sum[o];
        float inv = 1.0f / fmaxf((float)g_deg[n], 1.0f);
        float x3 = x2 * inv;
        float x4 = g_max[o];
        s2 += x2; q2 += x2 * x2;
        s3 += x3; q3 += x3 * x3;
        s4 += x4; q4 += x4 * x4;
    }
    atomicAdd(&g_SQ[2 * D + d], s2);
    atomicAdd(&g_SQ[(N_OPS + 2) * D + d], q2);
    atomicAdd(&g_SQ[3 * D + d], s3);
    atomicAdd(&g_SQ[(N_OPS + 3) * D + d], q3);
    atomicAdd(&g_SQ[4 * D + d], s4);
    atomicAdd(&g_SQ[(N_OPS + 4) * D + d], q4);
}

// ---------------- 7. fused coef + normalize + ReLU + weighted sum ---------
__global__ void k_final(const float* __restrict__ h, const float* __restrict__ hin,
                        const float* __restrict__ w,
                        const float* __restrict__ gamma,
                        const float* __restrict__ beta,
                        float* __restrict__ out) {
    __shared__ float sA[N_OPS * D];
    __shared__ float sC[N_OPS * D];
    for (int t = threadIdx.x; t < N_OPS * D; t += blockDim.x) {
        int b = t / D;
        float S = g_SQ[t];
        float Q = g_SQ[N_OPS * D + t];
        float mu   = S * (1.0f / N_NODES);
        float var  = fmaxf(Q * (1.0f / N_NODES) - mu * mu, 0.0f);
        float rstd = rsqrtf(var + EPS);
        float A = w[b] * gamma[t] * rstd;   // weights >= 0, fold inside ReLU
        sA[t] = A;
        sC[t] = w[b] * beta[t] - A * mu;
    }
    __syncthreads();

    int gid = blockIdx.x * blockDim.x + threadIdx.x;  // one float4 per thread
    if (gid >= N_NODES * (D / 4)) return;
    int n  = gid >> 5;
    int f4 = (gid & 31) * 4;
    size_t o = (size_t)n * D + f4;

    float4 x0 = *reinterpret_cast<const float4*>(h + o);
    float4 x1 = *reinterpret_cast<const float4*>(hin + o);
    float4 x2 = *reinterpret_cast<const float4*>(g_sum + o);
    float4 x4 = *reinterpret_cast<const float4*>(g_max + o);
    float inv = 1.0f / fmaxf((float)g_deg[n], 1.0f);
    float4 x3 = make_float4(x2.x * inv, x2.y * inv, x2.z * inv, x2.w * inv);

    float xs[N_OPS][4] = {
        {x0.x, x0.y, x0.z, x0.w},
        {x1.x, x1.y, x1.z, x1.w},
        {x2.x, x2.y, x2.z, x2.w},
        {x3.x, x3.y, x3.z, x3.w},
        {x4.x, x4.y, x4.z, x4.w},
    };
    float acc[4] = {0.f, 0.f, 0.f, 0.f};
    #pragma unroll
    for (int b = 0; b < N_OPS; b++) {
        #pragma unroll
        for (int c = 0; c < 4; c++) {
            float A = sA[b * D + f4 + c];
            float C = sC[b * D + f4 + c];
            acc[c] += fmaxf(fmaf(A, xs[b][c], C), 0.0f);
        }
    }
    *reinterpret_cast<float4*>(out + o) = make_float4(acc[0], acc[1], acc[2], acc[3]);
}

// ---------------- launch ---------------------------------------------------
extern "C" void kernel_launch(void* const* d_in, const int* in_sizes, int n_in,
                              void* d_out, int out_size) {
    const float* weights = (const float*)d_in[0];
    const void*  ei      = d_in[1];                 // int32 or int64, detected on-device
    const float* h       = (const float*)d_in[2];
    const float* hin     = (const float*)d_in[3];
    const float* gamma   = (const float*)d_in[4];
    const float* beta    = (const float*)d_in[5];
    float*       out     = (float*)d_out;

    k_init<<<(N_NODES + 255) / 256, 256>>>((const long long*)ei);
    k_hist_st<<<STAT_BLOCKS + HIST_BLOCKS, 256>>>(ei, h, hin);
    k_scan<<<SCAN_BLOCKS, 256>>>();
    k_fill<<<(N_EDGES + 255) / 256, 256>>>(ei);
    k_agg<<<(N_NODES * 32 + 255) / 256, 256>>>(h);
    k_stats2<<<STAT_BLOCKS, 256>>>();
    k_final<<<(N_NODES * (D / 4) + 255) / 256, 256>>>(h, hin, weights, gamma, beta, out);
}